// round 2
// baseline (speedup 1.0000x reference)
#include <cuda_runtime.h>
#include <cstddef>

// ---------------------------------------------------------------------------
// Problem constants
// ---------------------------------------------------------------------------
#define N_BATCH 64
#define M0 4096
#define M1 1024
#define K_CHEB 25
#define F0 32
#define F1 64
#define NC1 64
#define NC2 2048
#define SL1 (M0*NC1)    // 262144 floats per T1 slab
#define SL2 (M1*NC2)    // 2097152 floats per T2 slab
#define Z1 16           // layer-1 split-K factor
#define KZ1 (M0/Z1)     // 256

// ---------------------------------------------------------------------------
// Device scratch
// ---------------------------------------------------------------------------
__device__ float g_T1[K_CHEB * SL1];            // 26.2 MB
__device__ float g_T2[(size_t)K_CHEB * SL2];    // 209.7 MB
__device__ float g_PZ[Z1 * SL1];                // 16 MB split-K partials (layer1)
__device__ float g_OUT2[N_BATCH * 16384];
__device__ float g_P[8 * N_BATCH * 512];
__device__ float g_Yh[N_BATCH * 512];

typedef unsigned long long u64;

__device__ __forceinline__ void ffma2(u64& d, u64 a, u64 b)
{
    asm("fma.rn.f32x2 %0, %1, %2, %0;" : "+l"(d) : "l"(a), "l"(b));
}
__device__ __forceinline__ float2 up2(u64 v)
{
    float2 f;
    asm("mov.b64 {%0, %1}, %2;" : "=f"(f.x), "=f"(f.y) : "l"(v));
    return f;
}

// ---------------------------------------------------------------------------
// Transpose x (N,4096) -> T1 slab 0 as [u][n]
// ---------------------------------------------------------------------------
__global__ void transpose_x(const float* __restrict__ x, float* __restrict__ T0)
{
    __shared__ float s[32][33];
    int u0 = blockIdx.x * 32, n0 = blockIdx.y * 32;
    int tx = threadIdx.x, ty = threadIdx.y;
    for (int r = ty; r < 32; r += 8)
        s[r][tx] = x[(size_t)(n0 + r) * M0 + u0 + tx];
    __syncthreads();
    for (int r = ty; r < 32; r += 8)
        T0[(size_t)(u0 + r) * NC1 + n0 + tx] = s[tx][r];
}

// ---------------------------------------------------------------------------
// Chebyshev GEMM with packed f32x2 FMAs.
//   PARTIAL=1 : writes raw partial sums to Cp (split-K, slab = M*NC per z)
//   PARTIAL=0 : C = s2 * (L @ B) - (hasA ? A : 0)
// L-tile stored DUPLICATED in smem so LDS.128 yields packed broadcast pairs.
// 256 threads, micro-tile MR x NR per thread.
// ---------------------------------------------------------------------------
#define GEMM2_COMPUTE()                                                       \
    do {                                                                      \
        _Pragma("unroll")                                                     \
        for (int kk = 0; kk < TK; kk++) {                                     \
            ulonglong2 a2[MR / 2];                                            \
            _Pragma("unroll")                                                 \
            for (int mg = 0; mg < MR / 2; mg++)                               \
                a2[mg] = *(const ulonglong2*)&Lsd[kk * LSTR + 2 * trow + 4 * mg]; \
            ulonglong2 b2[NR / 4];                                            \
            _Pragma("unroll")                                                 \
            for (int ng = 0; ng < NR / 4; ng++)                               \
                b2[ng] = *(const ulonglong2*)&Bs[kk * TN + tcol * NR + 4 * ng];  \
            _Pragma("unroll")                                                 \
            for (int m = 0; m < MR; m++) {                                    \
                u64 av = (m & 1) ? a2[m / 2].y : a2[m / 2].x;                 \
                _Pragma("unroll")                                             \
                for (int p = 0; p < NR / 2; p++) {                            \
                    u64 bb = (p & 1) ? b2[p / 2].y : b2[p / 2].x;             \
                    ffma2(acc[m][p], av, bb);                                 \
                }                                                             \
            }                                                                 \
        }                                                                     \
    } while (0)

template<int TM, int TN, int TK, int MR, int NR, int PARTIAL>
__global__ __launch_bounds__(256)
void cheb_gemm2(const float* __restrict__ Lp, const float* __restrict__ Bp,
                const float* __restrict__ Ap, float* __restrict__ Cp,
                int M, int NC, int KLEN, float s2, int hasA)
{
    constexpr int LSTR = 2 * TM + 4;
    constexpr int NL4  = TM * TK / 1024;
    constexpr int NB4  = TK * TN / 1024;
    __shared__ __align__(16) float Lsd[TK * LSTR];
    __shared__ __align__(16) float Bs[TK * TN];

    const int tid  = threadIdx.x;
    const int u0   = blockIdx.y * TM;
    const int j0   = blockIdx.x * TN;
    const int kz   = blockIdx.z * KLEN;
    const int tcol = tid % (TN / NR);
    const int trow = (tid / (TN / NR)) * MR;

    // L loader indices (float4 along k, row-major, coalesced)
    int lu[NL4], lk[NL4];
    const float* Lb[NL4];
#pragma unroll
    for (int t = 0; t < NL4; t++) {
        int idx = tid * 4 + t * 1024;
        lu[t] = idx / TK;
        lk[t] = idx % TK;
        Lb[t] = Lp + (size_t)(u0 + lu[t]) * M + kz + lk[t];
    }
    // B loader indices
    int brr[NB4], bcc[NB4];
    const float* Bb[NB4];
#pragma unroll
    for (int t = 0; t < NB4; t++) {
        int idx = tid * 4 + t * 1024;
        brr[t] = idx / TN;
        bcc[t] = idx % TN;
        Bb[t] = Bp + (size_t)(kz + brr[t]) * NC + j0 + bcc[t];
    }

    u64 acc[MR][NR / 2];
#pragma unroll
    for (int m = 0; m < MR; m++)
#pragma unroll
        for (int p = 0; p < NR / 2; p++) acc[m][p] = 0ull;

    float4 lv[NL4], bv[NB4];
#pragma unroll
    for (int t = 0; t < NL4; t++) lv[t] = *(const float4*)(Lb[t]);
#pragma unroll
    for (int t = 0; t < NB4; t++) bv[t] = *(const float4*)(Bb[t]);

#pragma unroll
    for (int t = 0; t < NL4; t++) {
        float* d = &Lsd[lk[t] * LSTR + 2 * lu[t]];
        *(float2*)(d + 0 * LSTR) = make_float2(lv[t].x, lv[t].x);
        *(float2*)(d + 1 * LSTR) = make_float2(lv[t].y, lv[t].y);
        *(float2*)(d + 2 * LSTR) = make_float2(lv[t].z, lv[t].z);
        *(float2*)(d + 3 * LSTR) = make_float2(lv[t].w, lv[t].w);
    }
#pragma unroll
    for (int t = 0; t < NB4; t++)
        *(float4*)&Bs[brr[t] * TN + bcc[t]] = bv[t];
    __syncthreads();

    for (int k0 = TK; k0 < KLEN; k0 += TK) {
#pragma unroll
        for (int t = 0; t < NL4; t++) lv[t] = *(const float4*)(Lb[t] + k0);
#pragma unroll
        for (int t = 0; t < NB4; t++) bv[t] = *(const float4*)(Bb[t] + (size_t)k0 * NC);

        GEMM2_COMPUTE();
        __syncthreads();

#pragma unroll
        for (int t = 0; t < NL4; t++) {
            float* d = &Lsd[lk[t] * LSTR + 2 * lu[t]];
            *(float2*)(d + 0 * LSTR) = make_float2(lv[t].x, lv[t].x);
            *(float2*)(d + 1 * LSTR) = make_float2(lv[t].y, lv[t].y);
            *(float2*)(d + 2 * LSTR) = make_float2(lv[t].z, lv[t].z);
            *(float2*)(d + 3 * LSTR) = make_float2(lv[t].w, lv[t].w);
        }
#pragma unroll
        for (int t = 0; t < NB4; t++)
            *(float4*)&Bs[brr[t] * TN + bcc[t]] = bv[t];
        __syncthreads();
    }
    GEMM2_COMPUTE();

    // epilogue
    size_t cbase = PARTIAL ? (size_t)blockIdx.z * M * NC : 0;
#pragma unroll
    for (int m = 0; m < MR; m++) {
        float2 f[NR / 2];
#pragma unroll
        for (int p = 0; p < NR / 2; p++) f[p] = up2(acc[m][p]);
        size_t off = cbase + (size_t)(u0 + trow + m) * NC + j0 + tcol * NR;
        if (PARTIAL) {
#pragma unroll
            for (int q = 0; q < NR / 4; q++)
                *(float4*)(Cp + off + 4 * q) =
                    make_float4(f[2 * q].x, f[2 * q].y, f[2 * q + 1].x, f[2 * q + 1].y);
        } else {
#pragma unroll
            for (int q = 0; q < NR / 4; q++) {
                float4 r = make_float4(s2 * f[2 * q].x,     s2 * f[2 * q].y,
                                       s2 * f[2 * q + 1].x, s2 * f[2 * q + 1].y);
                if (hasA) {
                    float4 a = *(const float4*)(Ap + off + 4 * q);
                    r.x -= a.x; r.y -= a.y; r.z -= a.z; r.w -= a.w;
                }
                *(float4*)(Cp + off + 4 * q) = r;
            }
        }
    }
}

// ---------------------------------------------------------------------------
// Split-K combine for layer1:  C = s2 * sum_z P[z] - (hasA ? A : 0)
// ---------------------------------------------------------------------------
__global__ __launch_bounds__(256)
void cheb_combine(const float* __restrict__ Ap, float* __restrict__ Cp,
                  float s2, int hasA)
{
    int i = blockIdx.x * blockDim.x + threadIdx.x;   // < SL1/4
    float4 s = make_float4(0.f, 0.f, 0.f, 0.f);
#pragma unroll
    for (int z = 0; z < Z1; z++) {
        float4 v = ((const float4*)g_PZ)[(size_t)z * (SL1 / 4) + i];
        s.x += v.x; s.y += v.y; s.z += v.z; s.w += v.w;
    }
    float4 r = make_float4(s2 * s.x, s2 * s.y, s2 * s.z, s2 * s.w);
    if (hasA) {
        float4 a = ((const float4*)Ap)[i];
        r.x -= a.x; r.y -= a.y; r.z -= a.z; r.w -= a.w;
    }
    ((float4*)Cp)[i] = r;
}

// ---------------------------------------------------------------------------
// Layer1 tail: relu(maxpool4(T1 @ W1) + b1) -> layer2 state 0
// ---------------------------------------------------------------------------
__global__ __launch_bounds__(256)
void layer1_pool(const float* __restrict__ W1, const float* __restrict__ b1)
{
    __shared__ float W1s[K_CHEB * F0];
    __shared__ float b1s[F0];
    int n   = threadIdx.x;
    int u1  = blockIdx.x * 4 + threadIdx.y;
    int tid = threadIdx.y * 64 + n;

    for (int i = tid; i < K_CHEB * F0; i += 256) W1s[i] = W1[i];
    if (tid < F0) b1s[tid] = b1[tid];
    __syncthreads();

    float m[F0];
#pragma unroll
    for (int f = 0; f < F0; f++) m[f] = -1e30f;

    for (int p = 0; p < 4; p++) {
        float acc[F0];
#pragma unroll
        for (int f = 0; f < F0; f++) acc[f] = 0.f;
        int u = u1 * 4 + p;
        const float* tp = g_T1 + (size_t)u * NC1 + n;
        for (int k = 0; k < K_CHEB; k++) {
            float t = tp[(size_t)k * SL1];
#pragma unroll
            for (int f = 0; f < F0; f++) acc[f] += t * W1s[k * F0 + f];
        }
#pragma unroll
        for (int f = 0; f < F0; f++) m[f] = fmaxf(m[f], acc[f]);
    }
    float* op = g_T2 + (size_t)u1 * NC2 + n * F0;
#pragma unroll
    for (int f = 0; f < F0; f++) op[f] = fmaxf(m[f] + b1s[f], 0.f);
}

// ---------------------------------------------------------------------------
// Layer2 tail: OUT2 = relu(maxpool4(T2_features @ W2) + b2)
// ---------------------------------------------------------------------------
__global__ __launch_bounds__(128)
void layer2_pool(const float* __restrict__ W2, const float* __restrict__ b2)
{
    extern __shared__ float Wall[];              // [800][32] for this f-half
    int n   = threadIdx.x;
    int u1  = blockIdx.x * 2 + threadIdx.y;
    int f0  = blockIdx.y * 32;
    int tid = threadIdx.y * 64 + n;

    for (int i = tid; i < 800 * 32; i += 128) {
        int r = i >> 5, f = i & 31;
        Wall[i] = W2[(size_t)r * F1 + f0 + f];
    }
    __syncthreads();

    float m[32];
#pragma unroll
    for (int f = 0; f < 32; f++) m[f] = -1e30f;

    for (int p = 0; p < 4; p++) {
        float acc[32];
#pragma unroll
        for (int f = 0; f < 32; f++) acc[f] = 0.f;
        int u = u1 * 4 + p;
        for (int k = 0; k < K_CHEB; k++) {
            const float4* tp = (const float4*)(g_T2 + (size_t)k * SL2 +
                                               (size_t)u * NC2 + n * F0);
#pragma unroll
            for (int c4 = 0; c4 < 8; c4++) {
                float4 t = tp[c4];
                const float* w0 = &Wall[((c4 * 4 + 0) * K_CHEB + k) * 32];
                const float* w1 = &Wall[((c4 * 4 + 1) * K_CHEB + k) * 32];
                const float* w2 = &Wall[((c4 * 4 + 2) * K_CHEB + k) * 32];
                const float* w3 = &Wall[((c4 * 4 + 3) * K_CHEB + k) * 32];
#pragma unroll
                for (int f = 0; f < 32; f++) {
                    acc[f] += t.x * w0[f];
                    acc[f] += t.y * w1[f];
                    acc[f] += t.z * w2[f];
                    acc[f] += t.w * w3[f];
                }
            }
        }
#pragma unroll
        for (int f = 0; f < 32; f++) m[f] = fmaxf(m[f], acc[f]);
    }
    float* op = g_OUT2 + (size_t)n * 16384 + u1 * F1 + f0;
#pragma unroll
    for (int f = 0; f < 32; f++) op[f] = fmaxf(m[f] + b2[f0 + f], 0.f);
}

// ---------------------------------------------------------------------------
// FC head
// ---------------------------------------------------------------------------
__global__ __launch_bounds__(256)
void fc1_partial(const float* __restrict__ Wh)
{
    __shared__ float As[32][68];
    __shared__ float Ws[32][32];
    int tid  = threadIdx.x;
    int j0   = blockIdx.x * 32;
    int kz   = blockIdx.y * 2048;
    int tcol = tid & 31;
    int n0   = (tid >> 5) * 8;
    float acc[8];
#pragma unroll
    for (int i = 0; i < 8; i++) acc[i] = 0.f;

    for (int k0 = 0; k0 < 2048; k0 += 32) {
        __syncthreads();
#pragma unroll
        for (int it = 0; it < 2; it++) {
            int idx = tid * 4 + it * 1024;
            int nn = idx >> 5;
            int kk = idx & 31;
            float4 v = *(const float4*)(g_OUT2 + (size_t)nn * 16384 + kz + k0 + kk);
            As[kk + 0][nn] = v.x; As[kk + 1][nn] = v.y;
            As[kk + 2][nn] = v.z; As[kk + 3][nn] = v.w;
        }
#pragma unroll
        for (int i = tid; i < 1024; i += 256) {
            int r = i >> 5, c = i & 31;
            Ws[r][c] = Wh[(size_t)(kz + k0 + r) * 512 + j0 + c];
        }
        __syncthreads();
#pragma unroll
        for (int kk = 0; kk < 32; kk++) {
            float w = Ws[kk][tcol];
            float4 a0 = *(const float4*)&As[kk][n0];
            float4 a1 = *(const float4*)&As[kk][n0 + 4];
            acc[0] += a0.x * w; acc[1] += a0.y * w;
            acc[2] += a0.z * w; acc[3] += a0.w * w;
            acc[4] += a1.x * w; acc[5] += a1.y * w;
            acc[6] += a1.z * w; acc[7] += a1.w * w;
        }
    }
#pragma unroll
    for (int i = 0; i < 8; i++)
        g_P[(size_t)blockIdx.y * 32768 + (size_t)(n0 + i) * 512 + j0 + tcol] = acc[i];
}

__global__ void fc1_reduce(const float* __restrict__ bh)
{
    int i = blockIdx.x * blockDim.x + threadIdx.x;
    float s = 0.f;
#pragma unroll
    for (int z = 0; z < 8; z++) s += g_P[(size_t)z * 32768 + i];
    g_Yh[i] = fmaxf(s + bh[i & 511], 0.f);
}

__global__ void fc2(const float* __restrict__ Wo, const float* __restrict__ bo,
                    float* __restrict__ out)
{
    int g = blockIdx.x * blockDim.x + threadIdx.x;
    if (g >= 640) return;
    int n = g / 10, o = g % 10;
    float s = bo[o];
    const float* y = g_Yh + (size_t)n * 512;
    for (int j = 0; j < 512; j++) s += y[j] * Wo[j * 10 + o];
    out[g] = s;
}

// ---------------------------------------------------------------------------
// Host driver
// ---------------------------------------------------------------------------
extern "C" void kernel_launch(void* const* d_in, const int* in_sizes, int n_in,
                              void* d_out, int out_size)
{
    const float* x  = (const float*)d_in[0];
    const float* L0 = (const float*)d_in[1];
    const float* L1 = (const float*)d_in[2];
    const float* W1 = (const float*)d_in[3];
    const float* b1 = (const float*)d_in[4];
    const float* W2 = (const float*)d_in[5];
    const float* b2 = (const float*)d_in[6];
    const float* Wh = (const float*)d_in[7];
    const float* bh = (const float*)d_in[8];
    const float* Wo = (const float*)d_in[9];
    const float* bo = (const float*)d_in[10];
    float* out = (float*)d_out;

    float *T1p, *T2p, *PZp;
    cudaGetSymbolAddress((void**)&T1p, g_T1);
    cudaGetSymbolAddress((void**)&T2p, g_T2);
    cudaGetSymbolAddress((void**)&PZp, g_PZ);

    // ---- layer 1 Chebyshev recurrence (split-K + combine) ----
    transpose_x<<<dim3(M0 / 32, N_BATCH / 32), dim3(32, 8)>>>(x, T1p);

    for (int k = 1; k < K_CHEB; k++) {
        cheb_gemm2<128, 64, 16, 4, 8, 1><<<dim3(1, M0 / 128, Z1), 256>>>(
            L0, T1p + (size_t)(k - 1) * SL1, nullptr, PZp, M0, NC1, KZ1, 0.f, 0);
        cheb_combine<<<SL1 / 1024, 256>>>(
            (k >= 2) ? T1p + (size_t)(k - 2) * SL1 : nullptr,
            T1p + (size_t)k * SL1, (k == 1) ? 1.f : 2.f, (k >= 2) ? 1 : 0);
    }

    // ---- layer 1 contraction + relu + pool -> layer2 state 0 ----
    layer1_pool<<<M1, dim3(64, 4)>>>(W1, b1);

    // ---- layer 2 Chebyshev recurrence ----
    cheb_gemm2<64, 128, 16, 4, 8, 0><<<dim3(NC2 / 128, M1 / 64, 1), 256>>>(
        L1, T2p, nullptr, T2p + SL2, M1, NC2, M1, 1.f, 0);
    for (int k = 2; k < K_CHEB; k++)
        cheb_gemm2<64, 128, 16, 4, 8, 0><<<dim3(NC2 / 128, M1 / 64, 1), 256>>>(
            L1, T2p + (size_t)(k - 1) * SL2, T2p + (size_t)(k - 2) * SL2,
            T2p + (size_t)k * SL2, M1, NC2, M1, 2.f, 1);

    // ---- layer 2 contraction + relu + pool ----
    cudaFuncSetAttribute(layer2_pool, cudaFuncAttributeMaxDynamicSharedMemorySize,
                         800 * 32 * 4);
    layer2_pool<<<dim3(128, 2), dim3(64, 2), 800 * 32 * 4>>>(W2, b2);

    // ---- FC head ----
    fc1_partial<<<dim3(16, 8), 256>>>(Wh);
    fc1_reduce<<<128, 256>>>(bh);
    fc2<<<5, 128>>>(Wo, bo, out);
}

// round 4
// speedup vs baseline: 1.0602x; 1.0602x over previous
#include <cuda_runtime.h>
#include <cstddef>

// ---------------------------------------------------------------------------
// Problem constants
// ---------------------------------------------------------------------------
#define N_BATCH 64
#define M0 4096
#define M1 1024
#define K_CHEB 25
#define F0 32
#define F1 64
#define NC1 64
#define NC2 2048
#define SL1 (M0*NC1)
#define SL2 (M1*NC2)
#define Z1 16
#define KZ1 (M0/Z1)

// ---------------------------------------------------------------------------
// Device scratch
// ---------------------------------------------------------------------------
__device__ float g_T1[K_CHEB * SL1];
__device__ float g_T2[(size_t)K_CHEB * SL2];
__device__ float g_PZ[Z1 * SL1];
__device__ float g_OUT2[N_BATCH * 16384];
__device__ float g_P[8 * N_BATCH * 512];
__device__ float g_Yh[N_BATCH * 512];

typedef unsigned long long u64;

__device__ __forceinline__ void ffma2(u64& d, u64 a, u64 b)
{
    asm("fma.rn.f32x2 %0, %1, %2, %0;" : "+l"(d) : "l"(a), "l"(b));
}
__device__ __forceinline__ float2 up2(u64 v)
{
    float2 f;
    asm("mov.b64 {%0, %1}, %2;" : "=f"(f.x), "=f"(f.y) : "l"(v));
    return f;
}
__device__ __forceinline__ u64 dupf(float f)
{
    u64 r;
    asm("mov.b64 %0, {%1, %1};" : "=l"(r) : "f"(f));
    return r;
}

// ---------------------------------------------------------------------------
// Transpose x (N,4096) -> T1 slab 0 as [u][n]
// ---------------------------------------------------------------------------
__global__ void transpose_x(const float* __restrict__ x, float* __restrict__ T0)
{
    __shared__ float s[32][33];
    int u0 = blockIdx.x * 32, n0 = blockIdx.y * 32;
    int tx = threadIdx.x, ty = threadIdx.y;
    for (int r = ty; r < 32; r += 8)
        s[r][tx] = x[(size_t)(n0 + r) * M0 + u0 + tx];
    __syncthreads();
    for (int r = ty; r < 32; r += 8)
        T0[(size_t)(u0 + r) * NC1 + n0 + tx] = s[tx][r];
}

// ---------------------------------------------------------------------------
// Chebyshev GEMM, f32x2 pairs along M, 4x8 micro-tile (moderate regs).
//  - L tile stored transposed [k][m] (m contiguous): one LDS.128 per thread
//    per kk yields 2 natural u64 row-pairs; only 4 distinct addresses per
//    warp -> ~1 shared wavefront.
//  - B tile [k][n]; scalars duplicated into (f,f) u64 pairs in registers.
//  PARTIAL=1: raw split-K partials to Cp slab z.  PARTIAL=0: C = s2*(L@B)-A.
// TM=128, TN=64, TK=16, 256 threads.
// ---------------------------------------------------------------------------
#define GEMM4_COMPUTE()                                                       \
    do {                                                                      \
        _Pragma("unroll")                                                     \
        for (int kk = 0; kk < TK; kk++) {                                     \
            ulonglong2 av = *(const ulonglong2*)&As[kk * ASTR + trow4];       \
            float4 q0 = *(const float4*)&Bs[kk * TN + tcol * 8];              \
            float4 q1 = *(const float4*)&Bs[kk * TN + tcol * 8 + 4];          \
            u64 bd[8];                                                        \
            bd[0] = dupf(q0.x); bd[1] = dupf(q0.y);                           \
            bd[2] = dupf(q0.z); bd[3] = dupf(q0.w);                           \
            bd[4] = dupf(q1.x); bd[5] = dupf(q1.y);                           \
            bd[6] = dupf(q1.z); bd[7] = dupf(q1.w);                           \
            _Pragma("unroll")                                                 \
            for (int n = 0; n < 8; n++) ffma2(acc[0][n], av.x, bd[n]);        \
            _Pragma("unroll")                                                 \
            for (int n = 0; n < 8; n++) ffma2(acc[1][n], av.y, bd[n]);        \
        }                                                                     \
    } while (0)

template<int PARTIAL>
__global__ __launch_bounds__(256)
void cheb_gemm4(const float* __restrict__ Lp, const float* __restrict__ Bp,
                const float* __restrict__ Ap, float* __restrict__ Cp,
                int M, int NC, int KLEN, float s2, int hasA)
{
    constexpr int TM = 128, TN = 64, TK = 16, NT = 256;
    constexpr int ASTR = TM + 4;
    constexpr int NL4  = TM * TK / (4 * NT);   // 2
    constexpr int NB4  = TK * TN / (4 * NT);   // 1
    __shared__ __align__(16) float As[TK * ASTR];
    __shared__ __align__(16) float Bs[TK * TN];

    const int tid   = threadIdx.x;
    const int u0    = blockIdx.y * TM;
    const int j0    = blockIdx.x * TN;
    const int kz    = blockIdx.z * KLEN;
    const int tcol  = tid % (TN / 8);          // 0..7
    const int trow4 = (tid / (TN / 8)) * 4;    // 0..124

    // L loader (float4 along k, row-major, coalesced; stored transposed)
    int lu[NL4], lk[NL4];
    const float* Lb[NL4];
#pragma unroll
    for (int t = 0; t < NL4; t++) {
        int idx = (tid + t * NT) * 4;
        lu[t] = idx / TK;
        lk[t] = idx % TK;
        Lb[t] = Lp + (size_t)(u0 + lu[t]) * M + kz + lk[t];
    }
    // B loader
    int brr[NB4], bcc[NB4];
    const float* Bb[NB4];
#pragma unroll
    for (int t = 0; t < NB4; t++) {
        int idx = (tid + t * NT) * 4;
        brr[t] = idx / TN;
        bcc[t] = idx % TN;
        Bb[t] = Bp + (size_t)(kz + brr[t]) * NC + j0 + bcc[t];
    }

    u64 acc[2][8];
#pragma unroll
    for (int mg = 0; mg < 2; mg++)
#pragma unroll
        for (int n = 0; n < 8; n++) acc[mg][n] = 0ull;

    float4 lv[NL4], bv[NB4];
#pragma unroll
    for (int t = 0; t < NL4; t++) lv[t] = *(const float4*)(Lb[t]);
#pragma unroll
    for (int t = 0; t < NB4; t++) bv[t] = *(const float4*)(Bb[t]);

#pragma unroll
    for (int t = 0; t < NL4; t++) {
        float* d = &As[lk[t] * ASTR + lu[t]];
        d[0 * ASTR] = lv[t].x; d[1 * ASTR] = lv[t].y;
        d[2 * ASTR] = lv[t].z; d[3 * ASTR] = lv[t].w;
    }
#pragma unroll
    for (int t = 0; t < NB4; t++)
        *(float4*)&Bs[brr[t] * TN + bcc[t]] = bv[t];
    __syncthreads();

    for (int k0 = TK; k0 < KLEN; k0 += TK) {
#pragma unroll
        for (int t = 0; t < NL4; t++) lv[t] = *(const float4*)(Lb[t] + k0);
#pragma unroll
        for (int t = 0; t < NB4; t++) bv[t] = *(const float4*)(Bb[t] + (size_t)k0 * NC);

        GEMM4_COMPUTE();
        __syncthreads();

#pragma unroll
        for (int t = 0; t < NL4; t++) {
            float* d = &As[lk[t] * ASTR + lu[t]];
            d[0 * ASTR] = lv[t].x; d[1 * ASTR] = lv[t].y;
            d[2 * ASTR] = lv[t].z; d[3 * ASTR] = lv[t].w;
        }
#pragma unroll
        for (int t = 0; t < NB4; t++)
            *(float4*)&Bs[brr[t] * TN + bcc[t]] = bv[t];
        __syncthreads();
    }
    GEMM4_COMPUTE();

    // epilogue: rows trow4..trow4+3, cols j0+tcol*8 .. +7
    size_t cbase = PARTIAL ? (size_t)blockIdx.z * M * NC : 0;
#pragma unroll
    for (int m = 0; m < 4; m++) {
        int mg = m >> 1, sel = m & 1;
        float v[8];
#pragma unroll
        for (int n = 0; n < 8; n++) {
            float2 f = up2(acc[mg][n]);
            v[n] = sel ? f.y : f.x;
        }
        size_t off = cbase + (size_t)(u0 + trow4 + m) * NC + j0 + tcol * 8;
        if (PARTIAL) {
            *(float4*)(Cp + off)     = make_float4(v[0], v[1], v[2], v[3]);
            *(float4*)(Cp + off + 4) = make_float4(v[4], v[5], v[6], v[7]);
        } else {
            float4 r0 = make_float4(s2 * v[0], s2 * v[1], s2 * v[2], s2 * v[3]);
            float4 r1 = make_float4(s2 * v[4], s2 * v[5], s2 * v[6], s2 * v[7]);
            if (hasA) {
                float4 a0 = *(const float4*)(Ap + off);
                float4 a1 = *(const float4*)(Ap + off + 4);
                r0.x -= a0.x; r0.y -= a0.y; r0.z -= a0.z; r0.w -= a0.w;
                r1.x -= a1.x; r1.y -= a1.y; r1.z -= a1.z; r1.w -= a1.w;
            }
            *(float4*)(Cp + off)     = r0;
            *(float4*)(Cp + off + 4) = r1;
        }
    }
}

// ---------------------------------------------------------------------------
// Split-K combine for layer1:  C = s2 * sum_z P[z] - (hasA ? A : 0)
// ---------------------------------------------------------------------------
__global__ __launch_bounds__(256)
void cheb_combine(const float* __restrict__ Ap, float* __restrict__ Cp,
                  float s2, int hasA)
{
    int i = blockIdx.x * blockDim.x + threadIdx.x;
    float4 s = make_float4(0.f, 0.f, 0.f, 0.f);
#pragma unroll
    for (int z = 0; z < Z1; z++) {
        float4 v = ((const float4*)g_PZ)[(size_t)z * (SL1 / 4) + i];
        s.x += v.x; s.y += v.y; s.z += v.z; s.w += v.w;
    }
    float4 r = make_float4(s2 * s.x, s2 * s.y, s2 * s.z, s2 * s.w);
    if (hasA) {
        float4 a = ((const float4*)Ap)[i];
        r.x -= a.x; r.y -= a.y; r.z -= a.z; r.w -= a.w;
    }
    ((float4*)Cp)[i] = r;
}

// ---------------------------------------------------------------------------
// Layer1 tail: relu(maxpool4(T1 @ W1) + b1) -> layer2 state 0
// ---------------------------------------------------------------------------
__global__ __launch_bounds__(256)
void layer1_pool(const float* __restrict__ W1, const float* __restrict__ b1)
{
    __shared__ float W1s[K_CHEB * F0];
    __shared__ float b1s[F0];
    int n   = threadIdx.x;
    int u1  = blockIdx.x * 4 + threadIdx.y;
    int tid = threadIdx.y * 64 + n;

    for (int i = tid; i < K_CHEB * F0; i += 256) W1s[i] = W1[i];
    if (tid < F0) b1s[tid] = b1[tid];
    __syncthreads();

    float m[F0];
#pragma unroll
    for (int f = 0; f < F0; f++) m[f] = -1e30f;

    for (int p = 0; p < 4; p++) {
        float acc[F0];
#pragma unroll
        for (int f = 0; f < F0; f++) acc[f] = 0.f;
        int u = u1 * 4 + p;
        const float* tp = g_T1 + (size_t)u * NC1 + n;
        for (int k = 0; k < K_CHEB; k++) {
            float t = tp[(size_t)k * SL1];
#pragma unroll
            for (int f = 0; f < F0; f++) acc[f] += t * W1s[k * F0 + f];
        }
#pragma unroll
        for (int f = 0; f < F0; f++) m[f] = fmaxf(m[f], acc[f]);
    }
    float* op = g_T2 + (size_t)u1 * NC2 + n * F0;
#pragma unroll
    for (int f = 0; f < F0; f++) op[f] = fmaxf(m[f] + b1s[f], 0.f);
}

// ---------------------------------------------------------------------------
// Layer2 tail: OUT2 = relu(maxpool4(T2_features @ W2) + b2)
// ---------------------------------------------------------------------------
__global__ __launch_bounds__(128)
void layer2_pool(const float* __restrict__ W2, const float* __restrict__ b2)
{
    extern __shared__ float Wall[];
    int n   = threadIdx.x;
    int u1  = blockIdx.x * 2 + threadIdx.y;
    int f0  = blockIdx.y * 32;
    int tid = threadIdx.y * 64 + n;

    for (int i = tid; i < 800 * 32; i += 128) {
        int r = i >> 5, f = i & 31;
        Wall[i] = W2[(size_t)r * F1 + f0 + f];
    }
    __syncthreads();

    float m[32];
#pragma unroll
    for (int f = 0; f < 32; f++) m[f] = -1e30f;

    for (int p = 0; p < 4; p++) {
        float acc[32];
#pragma unroll
        for (int f = 0; f < 32; f++) acc[f] = 0.f;
        int u = u1 * 4 + p;
        for (int k = 0; k < K_CHEB; k++) {
            const float4* tp = (const float4*)(g_T2 + (size_t)k * SL2 +
                                               (size_t)u * NC2 + n * F0);
#pragma unroll
            for (int c4 = 0; c4 < 8; c4++) {
                float4 t = tp[c4];
                const float* w0 = &Wall[((c4 * 4 + 0) * K_CHEB + k) * 32];
                const float* w1 = &Wall[((c4 * 4 + 1) * K_CHEB + k) * 32];
                const float* w2 = &Wall[((c4 * 4 + 2) * K_CHEB + k) * 32];
                const float* w3 = &Wall[((c4 * 4 + 3) * K_CHEB + k) * 32];
#pragma unroll
                for (int f = 0; f < 32; f++) {
                    acc[f] += t.x * w0[f];
                    acc[f] += t.y * w1[f];
                    acc[f] += t.z * w2[f];
                    acc[f] += t.w * w3[f];
                }
            }
        }
#pragma unroll
        for (int f = 0; f < 32; f++) m[f] = fmaxf(m[f], acc[f]);
    }
    float* op = g_OUT2 + (size_t)n * 16384 + u1 * F1 + f0;
#pragma unroll
    for (int f = 0; f < 32; f++) op[f] = fmaxf(m[f] + b2[f0 + f], 0.f);
}

// ---------------------------------------------------------------------------
// FC head
// ---------------------------------------------------------------------------
__global__ __launch_bounds__(256)
void fc1_partial(const float* __restrict__ Wh)
{
    __shared__ float As[32][68];
    __shared__ float Ws[32][32];
    int tid  = threadIdx.x;
    int j0   = blockIdx.x * 32;
    int kz   = blockIdx.y * 2048;
    int tcol = tid & 31;
    int n0   = (tid >> 5) * 8;
    float acc[8];
#pragma unroll
    for (int i = 0; i < 8; i++) acc[i] = 0.f;

    for (int k0 = 0; k0 < 2048; k0 += 32) {
        __syncthreads();
#pragma unroll
        for (int it = 0; it < 2; it++) {
            int idx = tid * 4 + it * 1024;
            int nn = idx >> 5;
            int kk = idx & 31;
            float4 v = *(const float4*)(g_OUT2 + (size_t)nn * 16384 + kz + k0 + kk);
            As[kk + 0][nn] = v.x; As[kk + 1][nn] = v.y;
            As[kk + 2][nn] = v.z; As[kk + 3][nn] = v.w;
        }
#pragma unroll
        for (int i = tid; i < 1024; i += 256) {
            int r = i >> 5, c = i & 31;
            Ws[r][c] = Wh[(size_t)(kz + k0 + r) * 512 + j0 + c];
        }
        __syncthreads();
#pragma unroll
        for (int kk = 0; kk < 32; kk++) {
            float w = Ws[kk][tcol];
            float4 a0 = *(const float4*)&As[kk][n0];
            float4 a1 = *(const float4*)&As[kk][n0 + 4];
            acc[0] += a0.x * w; acc[1] += a0.y * w;
            acc[2] += a0.z * w; acc[3] += a0.w * w;
            acc[4] += a1.x * w; acc[5] += a1.y * w;
            acc[6] += a1.z * w; acc[7] += a1.w * w;
        }
    }
#pragma unroll
    for (int i = 0; i < 8; i++)
        g_P[(size_t)blockIdx.y * 32768 + (size_t)(n0 + i) * 512 + j0 + tcol] = acc[i];
}

__global__ void fc1_reduce(const float* __restrict__ bh)
{
    int i = blockIdx.x * blockDim.x + threadIdx.x;
    float s = 0.f;
#pragma unroll
    for (int z = 0; z < 8; z++) s += g_P[(size_t)z * 32768 + i];
    g_Yh[i] = fmaxf(s + bh[i & 511], 0.f);
}

__global__ void fc2(const float* __restrict__ Wo, const float* __restrict__ bo,
                    float* __restrict__ out)
{
    int g = blockIdx.x * blockDim.x + threadIdx.x;
    if (g >= 640) return;
    int n = g / 10, o = g % 10;
    float s = bo[o];
    const float* y = g_Yh + (size_t)n * 512;
    for (int j = 0; j < 512; j++) s += y[j] * Wo[j * 10 + o];
    out[g] = s;
}

// ---------------------------------------------------------------------------
// Host driver
// ---------------------------------------------------------------------------
extern "C" void kernel_launch(void* const* d_in, const int* in_sizes, int n_in,
                              void* d_out, int out_size)
{
    const float* x  = (const float*)d_in[0];
    const float* L0 = (const float*)d_in[1];
    const float* L1 = (const float*)d_in[2];
    const float* W1 = (const float*)d_in[3];
    const float* b1 = (const float*)d_in[4];
    const float* W2 = (const float*)d_in[5];
    const float* b2 = (const float*)d_in[6];
    const float* Wh = (const float*)d_in[7];
    const float* bh = (const float*)d_in[8];
    const float* Wo = (const float*)d_in[9];
    const float* bo = (const float*)d_in[10];
    float* out = (float*)d_out;

    float *T1p, *T2p, *PZp;
    cudaGetSymbolAddress((void**)&T1p, g_T1);
    cudaGetSymbolAddress((void**)&T2p, g_T2);
    cudaGetSymbolAddress((void**)&PZp, g_PZ);

    // ---- layer 1 Chebyshev recurrence (split-K + combine) ----
    transpose_x<<<dim3(M0 / 32, N_BATCH / 32), dim3(32, 8)>>>(x, T1p);

    for (int k = 1; k < K_CHEB; k++) {
        cheb_gemm4<1><<<dim3(1, M0 / 128, Z1), 256>>>(
            L0, T1p + (size_t)(k - 1) * SL1, nullptr, PZp, M0, NC1, KZ1, 0.f, 0);
        cheb_combine<<<SL1 / 1024, 256>>>(
            (k >= 2) ? T1p + (size_t)(k - 2) * SL1 : nullptr,
            T1p + (size_t)k * SL1, (k == 1) ? 1.f : 2.f, (k >= 2) ? 1 : 0);
    }

    // ---- layer 1 contraction + relu + pool -> layer2 state 0 ----
    layer1_pool<<<M1, dim3(64, 4)>>>(W1, b1);

    // ---- layer 2 Chebyshev recurrence ----
    cheb_gemm4<0><<<dim3(NC2 / 64, M1 / 128, 1), 256>>>(
        L1, T2p, nullptr, T2p + SL2, M1, NC2, M1, 1.f, 0);
    for (int k = 2; k < K_CHEB; k++)
        cheb_gemm4<0><<<dim3(NC2 / 64, M1 / 128, 1), 256>>>(
            L1, T2p + (size_t)(k - 1) * SL2, T2p + (size_t)(k - 2) * SL2,
            T2p + (size_t)k * SL2, M1, NC2, M1, 2.f, 1);

    // ---- layer 2 contraction + relu + pool ----
    cudaFuncSetAttribute(layer2_pool, cudaFuncAttributeMaxDynamicSharedMemorySize,
                         800 * 32 * 4);
    layer2_pool<<<dim3(128, 2), dim3(64, 2), 800 * 32 * 4>>>(W2, b2);

    // ---- FC head ----
    fc1_partial<<<dim3(16, 8), 256>>>(Wh);
    fc1_reduce<<<128, 256>>>(bh);
    fc2<<<5, 128>>>(Wo, bo, out);
}

// round 6
// speedup vs baseline: 2.3025x; 2.1718x over previous
#include <cuda_runtime.h>
#include <cuda_bf16.h>
#include <cstdint>
#include <cstddef>

// ---------------------------------------------------------------------------
// Problem constants
// ---------------------------------------------------------------------------
#define N_BATCH 64
#define M0 4096
#define M1 1024
#define K_CHEB 25
#define F0 32
#define F1 64
#define NC1 64
#define NC2 2048
#define SL1 (M0*NC1)
#define SL2 (M1*NC2)
#define Z1 8
#define KZ1 (M0/Z1)     // 512

// ---------------------------------------------------------------------------
// Device scratch
// ---------------------------------------------------------------------------
__device__ float g_T1[K_CHEB * SL1];
__device__ float g_T2[(size_t)K_CHEB * SL2];
__device__ float g_PZ[(size_t)Z1 * SL1];
__device__ float g_OUT2[N_BATCH * 16384];
__device__ float g_P[8 * N_BATCH * 512];
__device__ float g_Yh[N_BATCH * 512];
__device__ __nv_bfloat16 g_L0h[(size_t)M0 * M0];
__device__ __nv_bfloat16 g_L0l[(size_t)M0 * M0];
__device__ __nv_bfloat16 g_L1h[(size_t)M1 * M1];
__device__ __nv_bfloat16 g_L1l[(size_t)M1 * M1];

// ---------------------------------------------------------------------------
// MMA helpers (portable Ampere-era tensor ops; no sm_103a-only features)
// ---------------------------------------------------------------------------
__device__ __forceinline__ uint32_t smem_u32(const void* p) {
    uint32_t a;
    asm("{ .reg .u64 t; cvta.to.shared.u64 t, %1; cvt.u32.u64 %0, t; }"
        : "=r"(a) : "l"(p));
    return a;
}
__device__ __forceinline__ void ldsm_x4(uint32_t* r, uint32_t addr) {
    asm volatile("ldmatrix.sync.aligned.m8n8.x4.shared.b16 {%0,%1,%2,%3}, [%4];"
        : "=r"(r[0]), "=r"(r[1]), "=r"(r[2]), "=r"(r[3]) : "r"(addr));
}
__device__ __forceinline__ void ldsm_x2(uint32_t* r, uint32_t addr) {
    asm volatile("ldmatrix.sync.aligned.m8n8.x2.shared.b16 {%0,%1}, [%2];"
        : "=r"(r[0]), "=r"(r[1]) : "r"(addr));
}
__device__ __forceinline__ void mma16816(float* c, const uint32_t* a,
                                         const uint32_t* b) {
    asm volatile(
        "mma.sync.aligned.m16n8k16.row.col.f32.bf16.bf16.f32 "
        "{%0,%1,%2,%3}, {%4,%5,%6,%7}, {%8,%9}, {%0,%1,%2,%3};"
        : "+f"(c[0]), "+f"(c[1]), "+f"(c[2]), "+f"(c[3])
        : "r"(a[0]), "r"(a[1]), "r"(a[2]), "r"(a[3]), "r"(b[0]), "r"(b[1]));
}

__device__ __forceinline__ void split2(float a, float b, uint32_t& h2, uint32_t& l2)
{
    __nv_bfloat16 ha = __float2bfloat16(a), hb = __float2bfloat16(b);
    float ra = __bfloat162float(ha), rb = __bfloat162float(hb);
    __nv_bfloat16 la = __float2bfloat16(a - ra), lb = __float2bfloat16(b - rb);
    h2 = (uint32_t)__bfloat16_as_ushort(ha) | ((uint32_t)__bfloat16_as_ushort(hb) << 16);
    l2 = (uint32_t)__bfloat16_as_ushort(la) | ((uint32_t)__bfloat16_as_ushort(lb) << 16);
}

// ---------------------------------------------------------------------------
// Prep: split fp32 matrix -> bf16 hi/lo
// ---------------------------------------------------------------------------
__global__ void split_bf16(const float* __restrict__ src,
                           __nv_bfloat16* __restrict__ hi,
                           __nv_bfloat16* __restrict__ lo, int n4)
{
    int i = blockIdx.x * blockDim.x + threadIdx.x;
    if (i >= n4) return;
    float4 v = ((const float4*)src)[i];
    uint32_t h0, l0, h1, l1;
    split2(v.x, v.y, h0, l0);
    split2(v.z, v.w, h1, l1);
    ((uint2*)hi)[i] = make_uint2(h0, h1);
    ((uint2*)lo)[i] = make_uint2(l0, l1);
}

// ---------------------------------------------------------------------------
// Transpose x (N,4096) -> T1 slab 0 as [u][n]
// ---------------------------------------------------------------------------
__global__ void transpose_x(const float* __restrict__ x, float* __restrict__ T0)
{
    __shared__ float s[32][33];
    int u0 = blockIdx.x * 32, n0 = blockIdx.y * 32;
    int tx = threadIdx.x, ty = threadIdx.y;
    for (int r = ty; r < 32; r += 8)
        s[r][tx] = x[(size_t)(n0 + r) * M0 + u0 + tx];
    __syncthreads();
    for (int r = ty; r < 32; r += 8)
        T0[(size_t)(u0 + r) * NC1 + n0 + tx] = s[tx][r];
}

// ---------------------------------------------------------------------------
// Tensor-core (mma.sync) Chebyshev GEMM step.
//   D[128,64] = L[u0:+128, kz:+KLEN] @ B[kz:+KLEN, j0:+64]
// Split-bf16 3-product: Lhi*Bhi + Lhi*Blo + Llo*Bhi, fp32 register accums.
//   A smem: [m][k] rows padded to 40 bf16 (80B) - conflict-free ldmatrix.
//   B smem: [n][k] rows padded to 40 bf16, built by on-the-fly fp32->bf16
//           hi/lo split + transpose of the state tile.
//   PARTIAL=1: raw D -> Cp slab blockIdx.z.  PARTIAL=0: C = s2*D - hasA*A.
// Block 256 threads = 8 warps (2 M x 4 N), warp tile 64x16, KT=32 per stage.
// ---------------------------------------------------------------------------
#define ASTR 40   // bf16 elems per A row (32 data + 8 pad) = 80B
#define BSTR 40

template<int PARTIAL>
__global__ __launch_bounds__(256)
void cheb_gemm_mma(const __nv_bfloat16* __restrict__ Lh,
                   const __nv_bfloat16* __restrict__ Ll,
                   const float* __restrict__ Bp,
                   const float* __restrict__ Ap,
                   float* __restrict__ Cp,
                   int M, int NC, int KLEN, float s2, int hasA)
{
    __shared__ __align__(16) __nv_bfloat16 sAh[128 * ASTR];
    __shared__ __align__(16) __nv_bfloat16 sAl[128 * ASTR];
    __shared__ __align__(16) __nv_bfloat16 sBh[64 * BSTR];
    __shared__ __align__(16) __nv_bfloat16 sBl[64 * BSTR];

    const int tid  = threadIdx.x;
    const int lane = tid & 31;
    const int wid  = tid >> 5;
    const int wm   = wid & 1;        // 2 M-blocks of 64
    const int wn   = wid >> 1;       // 4 N-blocks of 16
    const int u0   = blockIdx.y * 128;
    const int j0   = blockIdx.x * 64;
    const int kz   = blockIdx.z * KLEN;
    const int KT   = KLEN >> 5;      // 32-wide k tiles

    // ---- loader indices ----
    // A: 2 uint4 (8 bf16) chunks per thread per (hi|lo) tile
    const int ar[2] = { (tid + 0)   >> 2, (tid + 256) >> 2 };
    const int acx[2] = { (tid & 3) * 8, (tid & 3) * 8 };
    // B: thread covers rows vp, vp+1 and 4 cols jb..jb+3 of the fp32 tile
    const int jb = (tid & 15) * 4;
    const int vp = (tid >> 4) * 2;

    // ---- ldmatrix base offsets ----
    const uint32_t aAh = smem_u32(sAh), aAl = smem_u32(sAl);
    const uint32_t aBh = smem_u32(sBh), aBl = smem_u32(sBl);
    const uint32_t arow = (uint32_t)((wm * 64 + (lane & 15)) * (ASTR * 2)
                                     + (lane >> 4) * 16);
    const uint32_t brow = (uint32_t)((wn * 16 + (lane & 7)) * (BSTR * 2)
                                     + ((lane >> 3) & 1) * 16);

    float acc[4][2][4];
#pragma unroll
    for (int ma = 0; ma < 4; ma++)
#pragma unroll
        for (int na = 0; na < 2; na++)
#pragma unroll
            for (int q = 0; q < 4; q++) acc[ma][na][q] = 0.f;

    uint4 avh[2], avl[2];
    float4 bv0, bv1;

    // prefetch tile 0
#pragma unroll
    for (int s = 0; s < 2; s++) {
        size_t off = (size_t)(u0 + ar[s]) * M + kz + acx[s];
        avh[s] = *(const uint4*)(Lh + off);
        avl[s] = *(const uint4*)(Ll + off);
    }
    bv0 = *(const float4*)(Bp + (size_t)(kz + vp) * NC + j0 + jb);
    bv1 = *(const float4*)(Bp + (size_t)(kz + vp + 1) * NC + j0 + jb);

#define STORE_TILE()                                                          \
    do {                                                                      \
        _Pragma("unroll")                                                     \
        for (int s = 0; s < 2; s++) {                                         \
            *(uint4*)&sAh[ar[s] * ASTR + acx[s]] = avh[s];                    \
            *(uint4*)&sAl[ar[s] * ASTR + acx[s]] = avl[s];                    \
        }                                                                     \
        const float* pa = (const float*)&bv0;                                 \
        const float* pb = (const float*)&bv1;                                 \
        _Pragma("unroll")                                                     \
        for (int jj = 0; jj < 4; jj++) {                                      \
            uint32_t h2, l2;                                                  \
            split2(pa[jj], pb[jj], h2, l2);                                   \
            *(uint32_t*)&sBh[(jb + jj) * BSTR + vp] = h2;                     \
            *(uint32_t*)&sBl[(jb + jj) * BSTR + vp] = l2;                     \
        }                                                                     \
    } while (0)

#define COMPUTE_TILE()                                                        \
    do {                                                                      \
        _Pragma("unroll")                                                     \
        for (int ss = 0; ss < 2; ss++) {                                      \
            uint32_t bh[2][2], blr[2][2];                                     \
            _Pragma("unroll")                                                 \
            for (int na = 0; na < 2; na++) {                                  \
                uint32_t boff = brow + na * 8 * (BSTR * 2) + ss * 32;         \
                ldsm_x2(bh[na],  aBh + boff);                                 \
                ldsm_x2(blr[na], aBl + boff);                                 \
            }                                                                 \
            _Pragma("unroll")                                                 \
            for (int ma = 0; ma < 4; ma++) {                                  \
                uint32_t ah[4], al[4];                                        \
                uint32_t aoff = arow + ma * 16 * (ASTR * 2) + ss * 32;        \
                ldsm_x4(ah, aAh + aoff);                                      \
                ldsm_x4(al, aAl + aoff);                                      \
                _Pragma("unroll")                                             \
                for (int na = 0; na < 2; na++) {                              \
                    mma16816(acc[ma][na], ah, bh[na]);                        \
                    mma16816(acc[ma][na], ah, blr[na]);                       \
                    mma16816(acc[ma][na], al, bh[na]);                        \
                }                                                             \
            }                                                                 \
        }                                                                     \
    } while (0)

    STORE_TILE();
    __syncthreads();

    for (int kt = 1; kt < KT; kt++) {
        // prefetch next
#pragma unroll
        for (int s = 0; s < 2; s++) {
            size_t off = (size_t)(u0 + ar[s]) * M + kz + kt * 32 + acx[s];
            avh[s] = *(const uint4*)(Lh + off);
            avl[s] = *(const uint4*)(Ll + off);
        }
        bv0 = *(const float4*)(Bp + (size_t)(kz + kt * 32 + vp) * NC + j0 + jb);
        bv1 = *(const float4*)(Bp + (size_t)(kz + kt * 32 + vp + 1) * NC + j0 + jb);

        COMPUTE_TILE();
        __syncthreads();
        STORE_TILE();
        __syncthreads();
    }
    COMPUTE_TILE();

    // ---- epilogue ----
    size_t cbase = PARTIAL ? (size_t)blockIdx.z * M * NC : 0;
#pragma unroll
    for (int ma = 0; ma < 4; ma++) {
#pragma unroll
        for (int na = 0; na < 2; na++) {
            int r0 = u0 + wm * 64 + ma * 16 + (lane >> 2);
            int c  = j0 + wn * 16 + na * 8 + (lane & 3) * 2;
            size_t o0 = (size_t)r0 * NC + c;
            size_t o1 = (size_t)(r0 + 8) * NC + c;
            float2 v0 = make_float2(acc[ma][na][0], acc[ma][na][1]);
            float2 v1 = make_float2(acc[ma][na][2], acc[ma][na][3]);
            if (PARTIAL) {
                *(float2*)(Cp + cbase + o0) = v0;
                *(float2*)(Cp + cbase + o1) = v1;
            } else {
                v0.x *= s2; v0.y *= s2; v1.x *= s2; v1.y *= s2;
                if (hasA) {
                    float2 a0 = *(const float2*)(Ap + o0);
                    float2 a1 = *(const float2*)(Ap + o1);
                    v0.x -= a0.x; v0.y -= a0.y;
                    v1.x -= a1.x; v1.y -= a1.y;
                }
                *(float2*)(Cp + o0) = v0;
                *(float2*)(Cp + o1) = v1;
            }
        }
    }
#undef STORE_TILE
#undef COMPUTE_TILE
}

// ---------------------------------------------------------------------------
// Split-K combine for layer1:  C = s2 * sum_z P[z] - (hasA ? A : 0)
// ---------------------------------------------------------------------------
__global__ __launch_bounds__(256)
void cheb_combine(const float* __restrict__ Ap, float* __restrict__ Cp,
                  float s2, int hasA)
{
    int i = blockIdx.x * blockDim.x + threadIdx.x;
    float4 s = make_float4(0.f, 0.f, 0.f, 0.f);
#pragma unroll
    for (int z = 0; z < Z1; z++) {
        float4 v = ((const float4*)g_PZ)[(size_t)z * (SL1 / 4) + i];
        s.x += v.x; s.y += v.y; s.z += v.z; s.w += v.w;
    }
    float4 r = make_float4(s2 * s.x, s2 * s.y, s2 * s.z, s2 * s.w);
    if (hasA) {
        float4 a = ((const float4*)Ap)[i];
        r.x -= a.x; r.y -= a.y; r.z -= a.z; r.w -= a.w;
    }
    ((float4*)Cp)[i] = r;
}

// ---------------------------------------------------------------------------
// Layer1 tail: relu(maxpool4(T1 @ W1) + b1) -> layer2 state 0
// ---------------------------------------------------------------------------
__global__ __launch_bounds__(256)
void layer1_pool(const float* __restrict__ W1, const float* __restrict__ b1)
{
    __shared__ float W1s[K_CHEB * F0];
    __shared__ float b1s[F0];
    int n   = threadIdx.x;
    int u1  = blockIdx.x * 4 + threadIdx.y;
    int tid = threadIdx.y * 64 + n;

    for (int i = tid; i < K_CHEB * F0; i += 256) W1s[i] = W1[i];
    if (tid < F0) b1s[tid] = b1[tid];
    __syncthreads();

    float m[F0];
#pragma unroll
    for (int f = 0; f < F0; f++) m[f] = -1e30f;

    for (int p = 0; p < 4; p++) {
        float acc[F0];
#pragma unroll
        for (int f = 0; f < F0; f++) acc[f] = 0.f;
        int u = u1 * 4 + p;
        const float* tp = g_T1 + (size_t)u * NC1 + n;
        for (int k = 0; k < K_CHEB; k++) {
            float t = tp[(size_t)k * SL1];
#pragma unroll
            for (int f = 0; f < F0; f++) acc[f] += t * W1s[k * F0 + f];
        }
#pragma unroll
        for (int f = 0; f < F0; f++) m[f] = fmaxf(m[f], acc[f]);
    }
    float* op = g_T2 + (size_t)u1 * NC2 + n * F0;
#pragma unroll
    for (int f = 0; f < F0; f++) op[f] = fmaxf(m[f] + b1s[f], 0.f);
}

// ---------------------------------------------------------------------------
// Layer2 tail: OUT2 = relu(maxpool4(T2_features @ W2) + b2)
// ---------------------------------------------------------------------------
__global__ __launch_bounds__(128)
void layer2_pool(const float* __restrict__ W2, const float* __restrict__ b2)
{
    extern __shared__ float Wall[];
    int n   = threadIdx.x;
    int u1  = blockIdx.x * 2 + threadIdx.y;
    int f0  = blockIdx.y * 32;
    int tid = threadIdx.y * 64 + n;

    for (int i = tid; i < 800 * 32; i += 128) {
        int r = i >> 5, f = i & 31;
        Wall[i] = W2[(size_t)r * F1 + f0 + f];
    }
    __syncthreads();

    float m[32];
#pragma unroll
    for (int f = 0; f < 32; f++) m[f] = -1e30f;

    for (int p = 0; p < 4; p++) {
        float acc[32];
#pragma unroll
        for (int f = 0; f < 32; f++) acc[f] = 0.f;
        int u = u1 * 4 + p;
        for (int k = 0; k < K_CHEB; k++) {
            const float4* tp = (const float4*)(g_T2 + (size_t)k * SL2 +
                                               (size_t)u * NC2 + n * F0);
#pragma unroll
            for (int c4 = 0; c4 < 8; c4++) {
                float4 t = tp[c4];
                const float* w0 = &Wall[((c4 * 4 + 0) * K_CHEB + k) * 32];
                const float* w1 = &Wall[((c4 * 4 + 1) * K_CHEB + k) * 32];
                const float* w2 = &Wall[((c4 * 4 + 2) * K_CHEB + k) * 32];
                const float* w3 = &Wall[((c4 * 4 + 3) * K_CHEB + k) * 32];
#pragma unroll
                for (int f = 0; f < 32; f++) {
                    acc[f] += t.x * w0[f];
                    acc[f] += t.y * w1[f];
                    acc[f] += t.z * w2[f];
                    acc[f] += t.w * w3[f];
                }
            }
        }
#pragma unroll
        for (int f = 0; f < 32; f++) m[f] = fmaxf(m[f], acc[f]);
    }
    float* op = g_OUT2 + (size_t)n * 16384 + u1 * F1 + f0;
#pragma unroll
    for (int f = 0; f < 32; f++) op[f] = fmaxf(m[f] + b2[f0 + f], 0.f);
}

// ---------------------------------------------------------------------------
// FC head
// ---------------------------------------------------------------------------
__global__ __launch_bounds__(256)
void fc1_partial(const float* __restrict__ Wh)
{
    __shared__ float As[32][68];
    __shared__ float Ws[32][32];
    int tid  = threadIdx.x;
    int j0   = blockIdx.x * 32;
    int kz   = blockIdx.y * 2048;
    int tcol = tid & 31;
    int n0   = (tid >> 5) * 8;
    float acc[8];
#pragma unroll
    for (int i = 0; i < 8; i++) acc[i] = 0.f;

    for (int k0 = 0; k0 < 2048; k0 += 32) {
        __syncthreads();
#pragma unroll
        for (int it = 0; it < 2; it++) {
            int idx = tid * 4 + it * 1024;
            int nn = idx >> 5;
            int kk = idx & 31;
            float4 v = *(const float4*)(g_OUT2 + (size_t)nn * 16384 + kz + k0 + kk);
            As[kk + 0][nn] = v.x; As[kk + 1][nn] = v.y;
            As[kk + 2][nn] = v.z; As[kk + 3][nn] = v.w;
        }
#pragma unroll
        for (int i = tid; i < 1024; i += 256) {
            int r = i >> 5, c = i & 31;
            Ws[r][c] = Wh[(size_t)(kz + k0 + r) * 512 + j0 + c];
        }
        __syncthreads();
#pragma unroll
        for (int kk = 0; kk < 32; kk++) {
            float w = Ws[kk][tcol];
            float4 a0 = *(const float4*)&As[kk][n0];
            float4 a1 = *(const float4*)&As[kk][n0 + 4];
            acc[0] += a0.x * w; acc[1] += a0.y * w;
            acc[2] += a0.z * w; acc[3] += a0.w * w;
            acc[4] += a1.x * w; acc[5] += a1.y * w;
            acc[6] += a1.z * w; acc[7] += a1.w * w;
        }
    }
#pragma unroll
    for (int i = 0; i < 8; i++)
        g_P[(size_t)blockIdx.y * 32768 + (size_t)(n0 + i) * 512 + j0 + tcol] = acc[i];
}

__global__ void fc1_reduce(const float* __restrict__ bh)
{
    int i = blockIdx.x * blockDim.x + threadIdx.x;
    float s = 0.f;
#pragma unroll
    for (int z = 0; z < 8; z++) s += g_P[(size_t)z * 32768 + i];
    g_Yh[i] = fmaxf(s + bh[i & 511], 0.f);
}

__global__ void fc2(const float* __restrict__ Wo, const float* __restrict__ bo,
                    float* __restrict__ out)
{
    int g = blockIdx.x * blockDim.x + threadIdx.x;
    if (g >= 640) return;
    int n = g / 10, o = g % 10;
    float s = bo[o];
    const float* y = g_Yh + (size_t)n * 512;
    for (int j = 0; j < 512; j++) s += y[j] * Wo[j * 10 + o];
    out[g] = s;
}

// ---------------------------------------------------------------------------
// Host driver
// ---------------------------------------------------------------------------
extern "C" void kernel_launch(void* const* d_in, const int* in_sizes, int n_in,
                              void* d_out, int out_size)
{
    const float* x  = (const float*)d_in[0];
    const float* L0 = (const float*)d_in[1];
    const float* L1 = (const float*)d_in[2];
    const float* W1 = (const float*)d_in[3];
    const float* b1 = (const float*)d_in[4];
    const float* W2 = (const float*)d_in[5];
    const float* b2 = (const float*)d_in[6];
    const float* Wh = (const float*)d_in[7];
    const float* bh = (const float*)d_in[8];
    const float* Wo = (const float*)d_in[9];
    const float* bo = (const float*)d_in[10];
    float* out = (float*)d_out;

    float *T1p, *T2p, *PZp;
    __nv_bfloat16 *L0h, *L0l, *L1h, *L1l;
    cudaGetSymbolAddress((void**)&T1p, g_T1);
    cudaGetSymbolAddress((void**)&T2p, g_T2);
    cudaGetSymbolAddress((void**)&PZp, g_PZ);
    cudaGetSymbolAddress((void**)&L0h, g_L0h);
    cudaGetSymbolAddress((void**)&L0l, g_L0l);
    cudaGetSymbolAddress((void**)&L1h, g_L1h);
    cudaGetSymbolAddress((void**)&L1l, g_L1l);

    // ---- prep: split L matrices into bf16 hi/lo ----
    split_bf16<<<(M0 * M0 / 4 + 255) / 256, 256>>>(L0, L0h, L0l, M0 * M0 / 4);
    split_bf16<<<(M1 * M1 / 4 + 255) / 256, 256>>>(L1, L1h, L1l, M1 * M1 / 4);

    // ---- layer 1 Chebyshev recurrence (tensor mma, split-K z=8) ----
    transpose_x<<<dim3(M0 / 32, N_BATCH / 32), dim3(32, 8)>>>(x, T1p);

    for (int k = 1; k < K_CHEB; k++) {
        cheb_gemm_mma<1><<<dim3(1, M0 / 128, Z1), 256>>>(
            L0h, L0l, T1p + (size_t)(k - 1) * SL1, nullptr, PZp,
            M0, NC1, KZ1, 0.f, 0);
        cheb_combine<<<SL1 / 1024, 256>>>(
            (k >= 2) ? T1p + (size_t)(k - 2) * SL1 : nullptr,
            T1p + (size_t)k * SL1, (k == 1) ? 1.f : 2.f, (k >= 2) ? 1 : 0);
    }

    // ---- layer 1 contraction + relu + pool -> layer2 state 0 ----
    layer1_pool<<<M1, dim3(64, 4)>>>(W1, b1);

    // ---- layer 2 Chebyshev recurrence (tensor mma) ----
    cheb_gemm_mma<0><<<dim3(NC2 / 64, M1 / 128, 1), 256>>>(
        L1h, L1l, T2p, nullptr, T2p + SL2, M1, NC2, M1, 1.f, 0);
    for (int k = 2; k < K_CHEB; k++)
        cheb_gemm_mma<0><<<dim3(NC2 / 64, M1 / 128, 1), 256>>>(
            L1h, L1l, T2p + (size_t)(k - 1) * SL2, T2p + (size_t)(k - 2) * SL2,
            T2p + (size_t)k * SL2, M1, NC2, M1, 2.f, 1);

    // ---- layer 2 contraction + relu + pool ----
    cudaFuncSetAttribute(layer2_pool, cudaFuncAttributeMaxDynamicSharedMemorySize,
                         800 * 32 * 4);
    layer2_pool<<<dim3(128, 2), dim3(64, 2), 800 * 32 * 4>>>(W2, b2);

    // ---- FC head ----
    fc1_partial<<<dim3(16, 8), 256>>>(Wh);
    fc1_reduce<<<128, 256>>>(bh);
    fc2<<<5, 128>>>(Wo, bo, out);
}